// round 1
// baseline (speedup 1.0000x reference)
#include <cuda_runtime.h>
#include <cuda_bf16.h>

typedef unsigned long long ull;

// Problem constants (match reference)
#define NB   256      // B*H batch-heads
#define TT   254      // T = L - 3 + 1
#define AUGS 148      // padded channel stride for aug
#define CH   145      // aug channels: 16 trunc + 1 time + 128 conv
#define SIGK 21170    // 145 + 145*145
#define SIGS 21184    // padded sig row stride (mult of 4)

// Scratch (no allocations allowed)
__device__ float g_aug[NB * TT * AUGS];   // ~38.5 MB
__device__ float g_sig[NB * SIGS];        // ~21.7 MB

// ---- packed f32x2 helpers (FFMA2 is PTX-only on sm_103a) ----
__device__ __forceinline__ ull pack2(float lo, float hi) {
    ull r; asm("mov.b64 %0, {%1, %2};" : "=l"(r) : "f"(lo), "f"(hi)); return r;
}
__device__ __forceinline__ void unpack2(ull v, float& lo, float& hi) {
    asm("mov.b64 {%0, %1}, %2;" : "=f"(lo), "=f"(hi) : "l"(v));
}
__device__ __forceinline__ void ffma2(ull& acc, ull a, ull b) {
    asm("fma.rn.f32x2 %0, %1, %2, %0;" : "+l"(acc) : "l"(a), "l"(b));
}

// ============================================================
// K1: conv1(k=3,16->64) + conv2(1x1,64->128,relu) + assemble aug
// one block per n, aug written to g_aug
// dynamic smem layout (floats):
//   sX[256*16]=0..4095, sW1[48*64]=4096..7167, sW2[64*128]=7168..15359,
//   sH[64*64]=15360..19455, sB1=19456..19519, sB2=19520..19647
// ============================================================
__global__ __launch_bounds__(256) void k_front(
    const float* __restrict__ q,
    const float* __restrict__ w1, const float* __restrict__ b1,
    const float* __restrict__ w2, const float* __restrict__ b2)
{
    extern __shared__ float sm[];
    float* sX  = sm;
    float* sW1 = sm + 4096;
    float* sW2 = sm + 7168;
    float* sH  = sm + 15360;
    float* sB1 = sm + 19456;
    float* sB2 = sm + 19520;

    int n = blockIdx.x, tid = threadIdx.x;
    int b = n >> 3, hh = n & 7;

    // load x[n] = q[b,:,hh,:]  (256 x 16)
    for (int idx = tid; idx < 4096; idx += 256) {
        int t = idx >> 4, e = idx & 15;
        sX[idx] = q[(((size_t)b * 256 + t) * 8 + hh) * 16 + e];
    }
    for (int idx = tid; idx < 3072; idx += 256) sW1[idx] = w1[idx];
    for (int idx = tid; idx < 8192; idx += 256) sW2[idx] = w2[idx];
    if (tid < 64) sB1[tid] = b1[tid];
    else if (tid < 192) sB2[tid - 64] = b2[tid - 64];
    __syncthreads();

    float* aug = g_aug + (size_t)n * (TT * AUGS);

    // trunc (x[:,2:]) + time channel
    for (int idx = tid; idx < TT * 17; idx += 256) {
        int t = idx / 17, c = idx - t * 17;
        aug[t * AUGS + c] = (c < 16) ? sX[(t + 2) * 16 + c]
                                     : (float)t * (1.0f / 253.0f);
    }

    for (int t0 = 0; t0 < TT; t0 += 64) {
        int tc = min(64, TT - t0);
        __syncthreads();
        // conv1: h[t][m], per thread one (t, m-pair), packed over m
        for (int idx = tid; idx < tc * 32; idx += 256) {
            int tl = idx >> 5, mp = idx & 31;
            const float* xr = sX + (t0 + tl) * 16;   // x[t+w][e] == xr[w*16+e]
            ull acc = pack2(sB1[2 * mp], sB1[2 * mp + 1]);
            #pragma unroll
            for (int we = 0; we < 48; we++) {
                float xv = xr[we];
                ffma2(acc, pack2(xv, xv), *(const ull*)&sW1[we * 64 + 2 * mp]);
            }
            *(ull*)&sH[tl * 64 + 2 * mp] = acc;
        }
        __syncthreads();
        // conv2 + relu: per thread 2 t x 4 c (weights reused across the 2 t)
        for (int idx = tid; idx < tc * 16; idx += 256) {
            int tq = idx >> 5, cq = idx & 31;
            int tl0 = 2 * tq, tl1 = 2 * tq + 1;
            ull a00 = pack2(sB2[4 * cq],     sB2[4 * cq + 1]);
            ull a01 = pack2(sB2[4 * cq + 2], sB2[4 * cq + 3]);
            ull a10 = a00, a11 = a01;
            #pragma unroll
            for (int m = 0; m < 64; m++) {
                ull w01 = *(const ull*)&sW2[m * 128 + 4 * cq];
                ull w23 = *(const ull*)&sW2[m * 128 + 4 * cq + 2];
                float h0 = sH[tl0 * 64 + m], h1 = sH[tl1 * 64 + m];
                ull h0p = pack2(h0, h0), h1p = pack2(h1, h1);
                ffma2(a00, h0p, w01); ffma2(a01, h0p, w23);
                ffma2(a10, h1p, w01); ffma2(a11, h1p, w23);
            }
            float v0, v1, v2, v3;
            float* r0 = aug + (t0 + tl0) * AUGS + 17 + 4 * cq;
            unpack2(a00, v0, v1); unpack2(a01, v2, v3);
            r0[0] = fmaxf(v0, 0.f); r0[1] = fmaxf(v1, 0.f);
            r0[2] = fmaxf(v2, 0.f); r0[3] = fmaxf(v3, 0.f);
            float* r1 = aug + (t0 + tl1) * AUGS + 17 + 4 * cq;
            unpack2(a10, v0, v1); unpack2(a11, v2, v3);
            r1[0] = fmaxf(v0, 0.f); r1[1] = fmaxf(v1, 0.f);
            r1[2] = fmaxf(v2, 0.f); r1[3] = fmaxf(v3, 0.f);
        }
    }
}

// ============================================================
// K2: depth-2 signature of aug (duplicated-point steps dropped):
//   d_t = aug[t+1]-aug[t]; u_t = 0.5(aug[t]+aug[t+1]) - aug[0]
//   S = sum_t u_t d_t^T  (145x145), plus s1 = aug[253]-aug[0]
// one block per n; thread tile 10 rows x 5 col-pairs (FFMA2)
// ============================================================
__global__ __launch_bounds__(256, 1) void k_sig()
{
    __shared__ float sU[32][160];
    __shared__ float sD[32][160];
    __shared__ float sA0[160];

    int n = blockIdx.x, tid = threadIdx.x;
    const float* aug = g_aug + (size_t)n * (TT * AUGS);
    float* sig = g_sig + (size_t)n * SIGS;

    // zero whole tiles once so pad columns (145..159) stay 0
    for (int idx = tid; idx < 32 * 160; idx += 256) {
        (&sU[0][0])[idx] = 0.f; (&sD[0][0])[idx] = 0.f;
    }
    for (int c = tid; c < 160; c += 256) sA0[c] = (c < CH) ? aug[c] : 0.f;
    if (tid < CH) sig[tid] = aug[253 * AUGS + tid] - aug[tid];   // s1
    __syncthreads();

    int ty = tid >> 4, tx = tid & 15;
    ull acc[10][5];
    #pragma unroll
    for (int r = 0; r < 10; r++)
        #pragma unroll
        for (int s = 0; s < 5; s++) acc[r][s] = 0ull;

    for (int t0 = 0; t0 < 253; t0 += 32) {
        int kc = min(32, 253 - t0);
        for (int idx = tid; idx < kc * CH; idx += 256) {
            int kk = idx / CH, c = idx - kk * CH;
            int t = t0 + kk;
            float a0v = aug[t * AUGS + c];
            float a1v = aug[(t + 1) * AUGS + c];
            sD[kk][c] = a1v - a0v;
            sU[kk][c] = 0.5f * (a0v + a1v) - sA0[c];
        }
        __syncthreads();
        for (int kk = 0; kk < kc; kk++) {
            ull d2[5];
            #pragma unroll
            for (int s = 0; s < 5; s++)
                d2[s] = *(const ull*)&sD[kk][2 * (tx + 16 * s)];
            #pragma unroll
            for (int r = 0; r < 10; r++) {
                float u = sU[kk][ty + 16 * r];
                ull uu = pack2(u, u);
                #pragma unroll
                for (int s = 0; s < 5; s++) ffma2(acc[r][s], uu, d2[s]);
            }
        }
        __syncthreads();
    }

    #pragma unroll
    for (int r = 0; r < 10; r++) {
        int i = ty + 16 * r;
        if (i >= CH) continue;
        float* row = sig + 145 + i * 145;
        #pragma unroll
        for (int s = 0; s < 5; s++) {
            int j = 2 * (tx + 16 * s);
            float lo, hi; unpack2(acc[r][s], lo, hi);
            if (j < CH)     row[j]     = lo;
            if (j + 1 < CH) row[j + 1] = hi;
        }
    }
}

// ============================================================
// K3a: out init with bias; K3b: split-K GEMM sig(256x21170) @ lin_w + atomics
// ============================================================
__global__ void k_bias(const float* __restrict__ lb, float* __restrict__ out)
{
    int i = blockIdx.x * 256 + threadIdx.x;   // 65536 outputs
    out[i] = lb[i & 255];
}

#define KLEN 1324   // ceil(21170/16)
__global__ __launch_bounds__(256) void k_gemm(
    const float* __restrict__ W, float* __restrict__ out)
{
    __shared__ float sA[16][65];
    __shared__ float sB[16][64];

    int n0 = blockIdx.x * 64, o0 = blockIdx.y * 64;
    int kb = blockIdx.z * KLEN;
    int ke = min(SIGK, kb + KLEN);
    int tid = threadIdx.x, ty = tid >> 4, tx = tid & 15;

    ull acc[4][2];
    #pragma unroll
    for (int i = 0; i < 4; i++) { acc[i][0] = 0ull; acc[i][1] = 0ull; }

    for (int k0 = kb; k0 < ke; k0 += 16) {
        for (int idx = tid; idx < 1024; idx += 256) {
            int kk = idx & 15, m = idx >> 4;
            int k = k0 + kk;
            sA[kk][m] = (k < ke) ? g_sig[(size_t)(n0 + m) * SIGS + k] : 0.f;
        }
        for (int idx = tid; idx < 1024; idx += 256) {
            int kk = idx >> 6, oo = idx & 63;
            int k = k0 + kk;
            sB[kk][oo] = (k < ke) ? W[(size_t)k * 256 + o0 + oo] : 0.f;
        }
        __syncthreads();
        #pragma unroll
        for (int kk = 0; kk < 16; kk++) {
            ull b0 = *(const ull*)&sB[kk][4 * tx];
            ull b1 = *(const ull*)&sB[kk][4 * tx + 2];
            #pragma unroll
            for (int i = 0; i < 4; i++) {
                float a = sA[kk][4 * ty + i];
                ull aa = pack2(a, a);
                ffma2(acc[i][0], aa, b0);
                ffma2(acc[i][1], aa, b1);
            }
        }
        __syncthreads();
    }

    #pragma unroll
    for (int i = 0; i < 4; i++) {
        float* orow = out + (size_t)(n0 + 4 * ty + i) * 256 + o0 + 4 * tx;
        float lo, hi;
        unpack2(acc[i][0], lo, hi);
        atomicAdd(&orow[0], lo); atomicAdd(&orow[1], hi);
        unpack2(acc[i][1], lo, hi);
        atomicAdd(&orow[2], lo); atomicAdd(&orow[3], hi);
    }
}

// ============================================================
extern "C" void kernel_launch(void* const* d_in, const int* in_sizes, int n_in,
                              void* d_out, int out_size)
{
    const float* q  = (const float*)d_in[0];
    // d_in[1]=k, d_in[2]=v, d_in[3]=mask: unused by the reference math
    const float* w1 = (const float*)d_in[4];
    const float* b1 = (const float*)d_in[5];
    const float* w2 = (const float*)d_in[6];
    const float* b2 = (const float*)d_in[7];
    const float* lw = (const float*)d_in[8];
    const float* lb = (const float*)d_in[9];
    float* out = (float*)d_out;

    cudaFuncSetAttribute(k_front, cudaFuncAttributeMaxDynamicSharedMemorySize,
                         19648 * 4);
    k_front<<<NB, 256, 19648 * 4>>>(q, w1, b1, w2, b2);
    k_sig<<<NB, 256>>>();
    k_bias<<<256, 256>>>(lb, out);
    k_gemm<<<dim3(4, 4, 16), 256>>>(lw, out);
}

// round 2
// speedup vs baseline: 1.1735x; 1.1735x over previous
#include <cuda_runtime.h>
#include <cuda_bf16.h>

typedef unsigned long long ull;

// Problem constants
#define NB   256      // B*H
#define TT   254      // T = L - 3 + 1
#define AUGS 148      // padded channel stride for aug
#define CH   145      // aug channels
#define SIGK 21170    // 145 + 145*145
#define SIGS 21184    // padded sig row stride (mult of 8)

// Scratch
__device__ float g_aug[NB * TT * AUGS];
__device__ float g_sig[NB * SIGS];

// ---- packed f32x2 helpers ----
__device__ __forceinline__ ull pack2(float lo, float hi) {
    ull r; asm("mov.b64 %0, {%1, %2};" : "=l"(r) : "f"(lo), "f"(hi)); return r;
}
__device__ __forceinline__ void unpack2(ull v, float& lo, float& hi) {
    asm("mov.b64 {%0, %1}, %2;" : "=f"(lo), "=f"(hi) : "l"(v));
}
__device__ __forceinline__ void ffma2(ull& acc, ull a, ull b) {
    asm("fma.rn.f32x2 %0, %1, %2, %0;" : "+l"(acc) : "l"(a), "l"(b));
}

// ============================================================
// K1: conv1(k=3,16->64) + conv2(1x1,64->128,relu) + assemble aug
// ============================================================
__global__ __launch_bounds__(256) void k_front(
    const float* __restrict__ q,
    const float* __restrict__ w1, const float* __restrict__ b1,
    const float* __restrict__ w2, const float* __restrict__ b2)
{
    extern __shared__ float sm[];
    float* sX  = sm;            // 4096
    float* sW1 = sm + 4096;     // 3072
    float* sW2 = sm + 7168;     // 8192
    float* sH  = sm + 15360;    // 4096
    float* sB1 = sm + 19456;    // 64
    float* sB2 = sm + 19520;    // 128

    int n = blockIdx.x, tid = threadIdx.x;
    int b = n >> 3, hh = n & 7;

    for (int idx = tid; idx < 4096; idx += 256) {
        int t = idx >> 4, e = idx & 15;
        sX[idx] = q[(((size_t)b * 256 + t) * 8 + hh) * 16 + e];
    }
    for (int idx = tid; idx < 3072; idx += 256) sW1[idx] = w1[idx];
    for (int idx = tid; idx < 8192; idx += 256) sW2[idx] = w2[idx];
    if (tid < 64) sB1[tid] = b1[tid];
    else if (tid < 192) sB2[tid - 64] = b2[tid - 64];
    __syncthreads();

    float* aug = g_aug + (size_t)n * (TT * AUGS);

    // trunc + time channel (no div: 2-D strided loop)
    for (int t = tid >> 5; t < TT; t += 8) {
        for (int c = tid & 31; c < 17; c += 32) {
            aug[t * AUGS + c] = (c < 16) ? sX[(t + 2) * 16 + c]
                                         : (float)t * (1.0f / 253.0f);
        }
    }

    for (int t0 = 0; t0 < TT; t0 += 64) {
        int tc = min(64, TT - t0);
        __syncthreads();
        // conv1
        for (int idx = tid; idx < tc * 32; idx += 256) {
            int tl = idx >> 5, mp = idx & 31;
            const float* xr = sX + (t0 + tl) * 16;
            ull acc = pack2(sB1[2 * mp], sB1[2 * mp + 1]);
            #pragma unroll
            for (int we = 0; we < 48; we++) {
                float xv = xr[we];
                ffma2(acc, pack2(xv, xv), *(const ull*)&sW1[we * 64 + 2 * mp]);
            }
            *(ull*)&sH[tl * 64 + 2 * mp] = acc;
        }
        __syncthreads();
        // conv2 + relu
        for (int idx = tid; idx < tc * 16; idx += 256) {
            int tq = idx >> 5, cq = idx & 31;
            int tl0 = 2 * tq, tl1 = 2 * tq + 1;
            ull a00 = pack2(sB2[4 * cq],     sB2[4 * cq + 1]);
            ull a01 = pack2(sB2[4 * cq + 2], sB2[4 * cq + 3]);
            ull a10 = a00, a11 = a01;
            #pragma unroll
            for (int m = 0; m < 64; m++) {
                ull w01 = *(const ull*)&sW2[m * 128 + 4 * cq];
                ull w23 = *(const ull*)&sW2[m * 128 + 4 * cq + 2];
                float h0 = sH[tl0 * 64 + m], h1 = sH[tl1 * 64 + m];
                ull h0p = pack2(h0, h0), h1p = pack2(h1, h1);
                ffma2(a00, h0p, w01); ffma2(a01, h0p, w23);
                ffma2(a10, h1p, w01); ffma2(a11, h1p, w23);
            }
            float v0, v1, v2, v3;
            float* r0 = aug + (t0 + tl0) * AUGS + 17 + 4 * cq;
            unpack2(a00, v0, v1); unpack2(a01, v2, v3);
            r0[0] = fmaxf(v0, 0.f); r0[1] = fmaxf(v1, 0.f);
            r0[2] = fmaxf(v2, 0.f); r0[3] = fmaxf(v3, 0.f);
            float* r1 = aug + (t0 + tl1) * AUGS + 17 + 4 * cq;
            unpack2(a10, v0, v1); unpack2(a11, v2, v3);
            r1[0] = fmaxf(v0, 0.f); r1[1] = fmaxf(v1, 0.f);
            r1[2] = fmaxf(v2, 0.f); r1[3] = fmaxf(v3, 0.f);
        }
    }
}

// ============================================================
// K2: depth-2 signature (dup-point steps dropped)
// ============================================================
__global__ __launch_bounds__(256) void k_sig()
{
    __shared__ float sU[32][160];
    __shared__ float sD[32][160];
    __shared__ float sA0[160];

    int n = blockIdx.x, tid = threadIdx.x;
    const float* aug = g_aug + (size_t)n * (TT * AUGS);
    float* sig = g_sig + (size_t)n * SIGS;

    for (int idx = tid; idx < 32 * 160; idx += 256) {
        (&sU[0][0])[idx] = 0.f; (&sD[0][0])[idx] = 0.f;
    }
    for (int c = tid; c < 160; c += 256) sA0[c] = (c < CH) ? aug[c] : 0.f;
    if (tid < CH) sig[tid] = aug[253 * AUGS + tid] - aug[tid];   // s1
    if (tid >= 192 && tid < 192 + (SIGS - SIGK)) sig[SIGK + (tid - 192)] = 0.f; // zero pad
    __syncthreads();

    int ty = tid >> 4, tx = tid & 15;
    ull acc[10][5];
    #pragma unroll
    for (int r = 0; r < 10; r++)
        #pragma unroll
        for (int s = 0; s < 5; s++) acc[r][s] = 0ull;

    for (int t0 = 0; t0 < 253; t0 += 32) {
        int kc = min(32, 253 - t0);
        // fill (no division, coalesced)
        for (int kk = tid >> 5; kk < kc; kk += 8) {
            const float* r0 = aug + (t0 + kk) * AUGS;
            for (int c = tid & 31; c < CH; c += 32) {
                float a0v = r0[c], a1v = r0[AUGS + c];
                sD[kk][c] = a1v - a0v;
                sU[kk][c] = 0.5f * (a0v + a1v) - sA0[c];
            }
        }
        __syncthreads();
        for (int kk = 0; kk < kc; kk++) {
            ull d2[5];
            #pragma unroll
            for (int s = 0; s < 5; s++)
                d2[s] = *(const ull*)&sD[kk][2 * (tx + 16 * s)];
            #pragma unroll
            for (int r = 0; r < 10; r++) {
                float u = sU[kk][ty + 16 * r];
                ull uu = pack2(u, u);
                #pragma unroll
                for (int s = 0; s < 5; s++) ffma2(acc[r][s], uu, d2[s]);
            }
        }
        __syncthreads();
    }

    #pragma unroll
    for (int r = 0; r < 10; r++) {
        int i = ty + 16 * r;
        if (i >= CH) continue;
        float* row = sig + 145 + i * 145;
        #pragma unroll
        for (int s = 0; s < 5; s++) {
            int j = 2 * (tx + 16 * s);
            float lo, hi; unpack2(acc[r][s], lo, hi);
            if (j < CH)     row[j]     = lo;
            if (j + 1 < CH) row[j + 1] = hi;
        }
    }
}

// ============================================================
// K3a: init out with bias
// ============================================================
__global__ void k_bias(const float* __restrict__ lb, float* __restrict__ out)
{
    int i = blockIdx.x * 256 + threadIdx.x;
    out[i] = lb[i & 255];
}

// ============================================================
// K3b: split-K GEMM  out += sig(256 x 21170) @ W(21170 x 256)
// 128x128 tile, 8x8 per thread, splitK=36 (one wave of 144 CTAs)
// ============================================================
#define SPLITK 36
#define KCH    592   // 36*592 = 21312 >= 21184, mult of 8

__global__ __launch_bounds__(256) void k_gemm(
    const float* __restrict__ W, float* __restrict__ out)
{
    __shared__ float sAd[8][264];   // duplicated A: (a,a) pairs, 128 rows -> 256+pad
    __shared__ float sB[8][132];

    int n0 = blockIdx.x * 128, o0 = blockIdx.y * 128;
    int kb = blockIdx.z * KCH;
    int kend = min(kb + KCH, SIGS);
    int tid = threadIdx.x, ty = tid >> 4, tx = tid & 15;

    // load indices
    int am = tid >> 1;            // row 0..127
    int ak = (tid & 1) * 4;       // k sub-offset 0 or 4
    int bk = tid >> 5;            // k row 0..7
    int bo = (tid & 31) * 4;      // col 0..124

    ull acc[8][4];
    #pragma unroll
    for (int i = 0; i < 8; i++)
        #pragma unroll
        for (int j = 0; j < 4; j++) acc[i][j] = 0ull;

    for (int k0 = kb; k0 < kend; k0 += 8) {
        // A tile: g_sig rows n0..n0+127, k0..k0+7 (pad cols are zeroed)
        float4 av = *(const float4*)&g_sig[(size_t)(n0 + am) * SIGS + k0 + ak];
        // B tile: W rows k0..k0+7, cols o0..o0+127 (guard k)
        float4 bv = make_float4(0.f, 0.f, 0.f, 0.f);
        if (k0 + bk < SIGK) bv = *(const float4*)&W[(size_t)(k0 + bk) * 256 + o0 + bo];

        {   // duplicated stores for A
            float* d = &sAd[ak][2 * am];
            d[0] = av.x; d[1] = av.x;
            d += 264;  d[0] = av.y; d[1] = av.y;
            d += 264;  d[0] = av.z; d[1] = av.z;
            d += 264;  d[0] = av.w; d[1] = av.w;
        }
        *(float4*)&sB[bk][bo] = bv;
        __syncthreads();

        #pragma unroll
        for (int kk = 0; kk < 8; kk++) {
            const float* arow = &sAd[kk][16 * ty];
            ull a[8];
            #pragma unroll
            for (int i = 0; i < 8; i++) a[i] = *(const ull*)(arow + 2 * i);
            ulonglong2 bl = *(const ulonglong2*)&sB[kk][4 * tx];
            ulonglong2 bh = *(const ulonglong2*)&sB[kk][64 + 4 * tx];
            #pragma unroll
            for (int i = 0; i < 8; i++) {
                ffma2(acc[i][0], a[i], bl.x);
                ffma2(acc[i][1], a[i], bl.y);
                ffma2(acc[i][2], a[i], bh.x);
                ffma2(acc[i][3], a[i], bh.y);
            }
        }
        __syncthreads();
    }

    #pragma unroll
    for (int i = 0; i < 8; i++) {
        float* orow = out + (size_t)(n0 + 8 * ty + i) * 256 + o0;
        #pragma unroll
        for (int j = 0; j < 4; j++) {
            int c = (j < 2) ? (4 * tx + 2 * j) : (64 + 4 * tx + 2 * (j - 2));
            float lo, hi; unpack2(acc[i][j], lo, hi);
            atomicAdd(&orow[c], lo);
            atomicAdd(&orow[c + 1], hi);
        }
    }
}

// ============================================================
extern "C" void kernel_launch(void* const* d_in, const int* in_sizes, int n_in,
                              void* d_out, int out_size)
{
    const float* q  = (const float*)d_in[0];
    const float* w1 = (const float*)d_in[4];
    const float* b1 = (const float*)d_in[5];
    const float* w2 = (const float*)d_in[6];
    const float* b2 = (const float*)d_in[7];
    const float* lw = (const float*)d_in[8];
    const float* lb = (const float*)d_in[9];
    float* out = (float*)d_out;

    cudaFuncSetAttribute(k_front, cudaFuncAttributeMaxDynamicSharedMemorySize,
                         19648 * 4);
    k_front<<<NB, 256, 19648 * 4>>>(q, w1, b1, w2, b2);
    k_sig<<<NB, 256>>>();
    k_bias<<<256, 256>>>(lb, out);
    k_gemm<<<dim3(2, 2, SPLITK), 256>>>(lw, out);
}

// round 3
// speedup vs baseline: 1.4361x; 1.2238x over previous
#include <cuda_runtime.h>
#include <cuda_bf16.h>

typedef unsigned long long ull;

#define NB   256
#define TT   254
#define AUGS 148
#define CH   145
#define SIGK 21170
#define SIGS 21184

__device__ float g_aug[NB * TT * AUGS];
__device__ float g_sig[NB * SIGS];

__device__ __forceinline__ ull pack2(float lo, float hi) {
    ull r; asm("mov.b64 %0, {%1, %2};" : "=l"(r) : "f"(lo), "f"(hi)); return r;
}
__device__ __forceinline__ void unpack2(ull v, float& lo, float& hi) {
    asm("mov.b64 {%0, %1}, %2;" : "=f"(lo), "=f"(hi) : "l"(v));
}
__device__ __forceinline__ void ffma2(ull& acc, ull a, ull b) {
    asm("fma.rn.f32x2 %0, %1, %2, %0;" : "+l"(acc) : "l"(a), "l"(b));
}

// ============================================================
// K1: conv1(3,16->64) + conv2(1x1,64->128,relu) + assemble aug
// ============================================================
__global__ __launch_bounds__(256) void k_front(
    const float* __restrict__ q,
    const float* __restrict__ w1, const float* __restrict__ b1,
    const float* __restrict__ w2, const float* __restrict__ b2)
{
    extern __shared__ float sm[];
    float* sX  = sm;            // 4096
    float* sW1 = sm + 4096;     // 3072
    float* sW2 = sm + 7168;     // 8192
    float* sH  = sm + 15360;    // 4096
    float* sB1 = sm + 19456;    // 64
    float* sB2 = sm + 19520;    // 128

    int n = blockIdx.x, tid = threadIdx.x;
    int b = n >> 3, hh = n & 7;

    for (int idx = tid; idx < 4096; idx += 256) {
        int t = idx >> 4, e = idx & 15;
        sX[idx] = q[(((size_t)b * 256 + t) * 8 + hh) * 16 + e];
    }
    for (int idx = tid; idx < 3072; idx += 256) sW1[idx] = w1[idx];
    for (int idx = tid; idx < 8192; idx += 256) sW2[idx] = w2[idx];
    if (tid < 64) sB1[tid] = b1[tid];
    else if (tid < 192) sB2[tid - 64] = b2[tid - 64];
    __syncthreads();

    float* aug = g_aug + (size_t)n * (TT * AUGS);

    for (int t = tid >> 5; t < TT; t += 8) {
        for (int c = tid & 31; c < 17; c += 32) {
            aug[t * AUGS + c] = (c < 16) ? sX[(t + 2) * 16 + c]
                                         : (float)t * (1.0f / 253.0f);
        }
    }

    for (int t0 = 0; t0 < TT; t0 += 64) {
        int tc = min(64, TT - t0);
        __syncthreads();
        for (int idx = tid; idx < tc * 32; idx += 256) {
            int tl = idx >> 5, mp = idx & 31;
            const float* xr = sX + (t0 + tl) * 16;
            ull acc = pack2(sB1[2 * mp], sB1[2 * mp + 1]);
            #pragma unroll
            for (int we = 0; we < 48; we++) {
                float xv = xr[we];
                ffma2(acc, pack2(xv, xv), *(const ull*)&sW1[we * 64 + 2 * mp]);
            }
            *(ull*)&sH[tl * 64 + 2 * mp] = acc;
        }
        __syncthreads();
        for (int idx = tid; idx < tc * 16; idx += 256) {
            int tq = idx >> 5, cq = idx & 31;
            int tl0 = 2 * tq, tl1 = 2 * tq + 1;
            ull a00 = pack2(sB2[4 * cq],     sB2[4 * cq + 1]);
            ull a01 = pack2(sB2[4 * cq + 2], sB2[4 * cq + 3]);
            ull a10 = a00, a11 = a01;
            #pragma unroll
            for (int m = 0; m < 64; m++) {
                ull w01 = *(const ull*)&sW2[m * 128 + 4 * cq];
                ull w23 = *(const ull*)&sW2[m * 128 + 4 * cq + 2];
                float h0 = sH[tl0 * 64 + m], h1 = sH[tl1 * 64 + m];
                ull h0p = pack2(h0, h0), h1p = pack2(h1, h1);
                ffma2(a00, h0p, w01); ffma2(a01, h0p, w23);
                ffma2(a10, h1p, w01); ffma2(a11, h1p, w23);
            }
            float v0, v1, v2, v3;
            float* r0 = aug + (t0 + tl0) * AUGS + 17 + 4 * cq;
            unpack2(a00, v0, v1); unpack2(a01, v2, v3);
            r0[0] = fmaxf(v0, 0.f); r0[1] = fmaxf(v1, 0.f);
            r0[2] = fmaxf(v2, 0.f); r0[3] = fmaxf(v3, 0.f);
            float* r1 = aug + (t0 + tl1) * AUGS + 17 + 4 * cq;
            unpack2(a10, v0, v1); unpack2(a11, v2, v3);
            r1[0] = fmaxf(v0, 0.f); r1[1] = fmaxf(v1, 0.f);
            r1[2] = fmaxf(v2, 0.f); r1[3] = fmaxf(v3, 0.f);
        }
    }
}

// ============================================================
// K2: signature S = sum_t u_t d_t^T, row-split across 2 blocks
// grid (NB, 2); block handles rows [80*ry, 80*ry+80) x cols 160
// ============================================================
__global__ __launch_bounds__(256, 2) void k_sig()
{
    __shared__ float sD[32][168];   // full 160 cols (+pad)
    __shared__ float sU[32][88];    // 80-row window (+pad)
    __shared__ float sA0[88];

    int n = blockIdx.x, tid = threadIdx.x;
    int r0 = blockIdx.y * 80;
    const float* aug = g_aug + (size_t)n * (TT * AUGS);
    float* sig = g_sig + (size_t)n * SIGS;

    for (int idx = tid; idx < 32 * 168; idx += 256) (&sD[0][0])[idx] = 0.f;
    for (int idx = tid; idx < 32 * 88;  idx += 256) (&sU[0][0])[idx] = 0.f;
    if (tid < 88) sA0[tid] = (tid < 80 && r0 + tid < CH) ? aug[r0 + tid] : 0.f;
    if (blockIdx.y == 0) {
        if (tid < CH) sig[tid] = aug[253 * AUGS + tid] - aug[tid];        // s1
        if (tid >= 192 && tid < 192 + (SIGS - SIGK)) sig[SIGK + (tid - 192)] = 0.f;
    }
    __syncthreads();

    int ty = tid >> 4, tx = tid & 15;
    ull acc[5][5];
    #pragma unroll
    for (int r = 0; r < 5; r++)
        #pragma unroll
        for (int s = 0; s < 5; s++) acc[r][s] = 0ull;

    for (int t0 = 0; t0 < 253; t0 += 32) {
        int kc = min(32, 253 - t0);
        for (int kk = tid >> 5; kk < kc; kk += 8) {
            const float* rr = aug + (t0 + kk) * AUGS;
            for (int c = tid & 31; c < CH; c += 32) {
                float a0v = rr[c], a1v = rr[AUGS + c];
                sD[kk][c] = a1v - a0v;
                unsigned cc = (unsigned)(c - r0);
                if (cc < 80u) sU[kk][cc] = 0.5f * (a0v + a1v) - sA0[cc];
            }
        }
        __syncthreads();
        for (int kk = 0; kk < kc; kk++) {
            ull d2[5];
            #pragma unroll
            for (int s = 0; s < 5; s++)
                d2[s] = *(const ull*)&sD[kk][2 * (tx + 16 * s)];
            #pragma unroll
            for (int r = 0; r < 5; r++) {
                float u = sU[kk][ty + 16 * r];
                ull uu = pack2(u, u);
                #pragma unroll
                for (int s = 0; s < 5; s++) ffma2(acc[r][s], uu, d2[s]);
            }
        }
        __syncthreads();
    }

    #pragma unroll
    for (int r = 0; r < 5; r++) {
        int i = r0 + ty + 16 * r;
        if (i >= CH) continue;
        float* row = sig + 145 + i * 145;
        #pragma unroll
        for (int s = 0; s < 5; s++) {
            int j = 2 * (tx + 16 * s);
            float lo, hi; unpack2(acc[r][s], lo, hi);
            if (j < CH)     row[j]     = lo;
            if (j + 1 < CH) row[j + 1] = hi;
        }
    }
}

// ============================================================
// K3a: init out with bias
// ============================================================
__global__ void k_bias(const float* __restrict__ lb, float* __restrict__ out)
{
    int i = blockIdx.x * 256 + threadIdx.x;
    out[i] = lb[i & 255];
}

// ============================================================
// K3b: split-K GEMM, double-buffered, splitK=72 (2 CTAs/SM)
// ============================================================
#define SPLITK 72
#define KCH    296   // 72*296 = 21312 >= 21184, mult of 8

__global__ __launch_bounds__(256, 2) void k_gemm(
    const float* __restrict__ W, float* __restrict__ out)
{
    __shared__ float sAd[2][8][264];
    __shared__ float sB[2][8][132];

    int n0 = blockIdx.x * 128, o0 = blockIdx.y * 128;
    int kb = blockIdx.z * KCH;
    int kend = min(kb + KCH, SIGS);
    int nk = (kend - kb) >> 3;
    int tid = threadIdx.x, ty = tid >> 4, tx = tid & 15;

    int am = tid >> 1;
    int ak = (tid & 1) * 4;
    int bk = tid >> 5;
    int bo = (tid & 31) * 4;

    const float* aptr = &g_sig[(size_t)(n0 + am) * SIGS + ak];
    const float* bptr = &W[(size_t)bk * 256 + o0 + bo];

    ull acc[8][4];
    #pragma unroll
    for (int i = 0; i < 8; i++)
        #pragma unroll
        for (int j = 0; j < 4; j++) acc[i][j] = 0ull;

    // prologue: load tile 0, store stage 0
    float4 av = *(const float4*)(aptr + kb);
    float4 bv = make_float4(0.f, 0.f, 0.f, 0.f);
    if (kb + bk < SIGK) bv = *(const float4*)(bptr + (size_t)kb * 256);
    {
        float* d = &sAd[0][ak][2 * am];
        d[0] = av.x; d[1] = av.x; d += 264; d[0] = av.y; d[1] = av.y;
        d += 264; d[0] = av.z; d[1] = av.z; d += 264; d[0] = av.w; d[1] = av.w;
        *(float4*)&sB[0][bk][bo] = bv;
    }

    for (int it = 0; it < nk; it++) {
        int cur = it & 1;
        float4 av2, bv2;
        if (it + 1 < nk) {
            int k0 = kb + 8 * (it + 1);
            av2 = *(const float4*)(aptr + k0);
            bv2 = make_float4(0.f, 0.f, 0.f, 0.f);
            if (k0 + bk < SIGK) bv2 = *(const float4*)(bptr + (size_t)k0 * 256);
        }
        __syncthreads();
        #pragma unroll
        for (int kk = 0; kk < 8; kk++) {
            const float* arow = &sAd[cur][kk][16 * ty];
            ull a[8];
            #pragma unroll
            for (int i = 0; i < 8; i++) a[i] = *(const ull*)(arow + 2 * i);
            ulonglong2 bl = *(const ulonglong2*)&sB[cur][kk][4 * tx];
            ulonglong2 bh = *(const ulonglong2*)&sB[cur][kk][64 + 4 * tx];
            #pragma unroll
            for (int i = 0; i < 8; i++) {
                ffma2(acc[i][0], a[i], bl.x);
                ffma2(acc[i][1], a[i], bl.y);
                ffma2(acc[i][2], a[i], bh.x);
                ffma2(acc[i][3], a[i], bh.y);
            }
        }
        if (it + 1 < nk) {
            int nxt = cur ^ 1;
            float* d = &sAd[nxt][ak][2 * am];
            d[0] = av2.x; d[1] = av2.x; d += 264; d[0] = av2.y; d[1] = av2.y;
            d += 264; d[0] = av2.z; d[1] = av2.z; d += 264; d[0] = av2.w; d[1] = av2.w;
            *(float4*)&sB[nxt][bk][bo] = bv2;
        }
    }

    #pragma unroll
    for (int i = 0; i < 8; i++) {
        float* orow = out + (size_t)(n0 + 8 * ty + i) * 256 + o0;
        #pragma unroll
        for (int j = 0; j < 4; j++) {
            int c = (j < 2) ? (4 * tx + 2 * j) : (64 + 4 * tx + 2 * (j - 2));
            float lo, hi; unpack2(acc[i][j], lo, hi);
            atomicAdd(&orow[c], lo);
            atomicAdd(&orow[c + 1], hi);
        }
    }
}

// ============================================================
extern "C" void kernel_launch(void* const* d_in, const int* in_sizes, int n_in,
                              void* d_out, int out_size)
{
    const float* q  = (const float*)d_in[0];
    const float* w1 = (const float*)d_in[4];
    const float* b1 = (const float*)d_in[5];
    const float* w2 = (const float*)d_in[6];
    const float* b2 = (const float*)d_in[7];
    const float* lw = (const float*)d_in[8];
    const float* lb = (const float*)d_in[9];
    float* out = (float*)d_out;

    cudaFuncSetAttribute(k_front, cudaFuncAttributeMaxDynamicSharedMemorySize,
                         19648 * 4);
    k_front<<<NB, 256, 19648 * 4>>>(q, w1, b1, w2, b2);
    k_sig<<<dim3(NB, 2), 256>>>();
    k_bias<<<256, 256>>>(lb, out);
    k_gemm<<<dim3(2, 2, SPLITK), 256>>>(lw, out);
}

// round 4
// speedup vs baseline: 1.9756x; 1.3757x over previous
#include <cuda_runtime.h>
#include <cuda_bf16.h>

typedef unsigned long long ull;

#define NB   256
#define TT   254
#define AUGS 148
#define CH   145
#define SIGK 21170
#define SIGS 21184

__device__ float g_aug[NB * TT * AUGS];
__device__ float g_sig[NB * SIGS];

__device__ __forceinline__ ull pack2(float lo, float hi) {
    ull r; asm("mov.b64 %0, {%1, %2};" : "=l"(r) : "f"(lo), "f"(hi)); return r;
}
__device__ __forceinline__ void unpack2(ull v, float& lo, float& hi) {
    asm("mov.b64 {%0, %1}, %2;" : "=f"(lo), "=f"(hi) : "l"(v));
}
__device__ __forceinline__ void ffma2(ull& acc, ull a, ull b) {
    asm("fma.rn.f32x2 %0, %1, %2, %0;" : "+l"(acc) : "l"(a), "l"(b));
}

// ============================================================
// K1: conv1(3,16->64) + conv2(1x1,64->128,relu) + assemble aug
// X and H kept DUPLICATED in smem so broadcast operand = 1 LDS.64
// ============================================================
__global__ __launch_bounds__(256) void k_front(
    const float* __restrict__ q,
    const float* __restrict__ w1, const float* __restrict__ b1,
    const float* __restrict__ w2, const float* __restrict__ b2)
{
    extern __shared__ float sm[];
    float* sXd = sm;              // 8192 (4096 values duplicated)
    float* sW1 = sm + 8192;       // 3072
    float* sW2 = sm + 11264;      // 8192
    float* sHd = sm + 19456;      // 64*140 = 8960 (dup, padded rows)
    float* sB1 = sm + 28416;      // 64
    float* sB2 = sm + 28480;      // 128   total 28608 floats

    int n = blockIdx.x, tid = threadIdx.x;
    int b = n >> 3, hh = n & 7;

    for (int idx = tid; idx < 4096; idx += 256) {
        int t = idx >> 4, e = idx & 15;
        float v = q[(((size_t)b * 256 + t) * 8 + hh) * 16 + e];
        *(ull*)&sXd[2 * idx] = pack2(v, v);
    }
    for (int idx = tid; idx < 3072; idx += 256) sW1[idx] = w1[idx];
    for (int idx = tid; idx < 8192; idx += 256) sW2[idx] = w2[idx];
    if (tid < 64) sB1[tid] = b1[tid];
    else if (tid < 192) sB2[tid - 64] = b2[tid - 64];
    __syncthreads();

    float* aug = g_aug + (size_t)n * (TT * AUGS);

    // trunc + time channels
    for (int t = tid >> 5; t < TT; t += 8) {
        for (int c = tid & 31; c < 17; c += 32) {
            aug[t * AUGS + c] = (c < 16) ? sXd[2 * ((t + 2) * 16 + c)]
                                         : (float)t * (1.0f / 253.0f);
        }
    }

    int mg = tid & 7,  tg  = tid >> 3;   // conv1: 2 t x 4 m-pairs
    int cg = tid & 15, tgq = tid >> 4;   // conv2: 4 t x 4 c-pairs

    for (int t0 = 0; t0 < TT; t0 += 64) {
        int tc = min(64, TT - t0);
        __syncthreads();
        // ---- conv1 ----
        {
            ull acc[2][4];
            #pragma unroll
            for (int j = 0; j < 4; j++) {
                ull bia = pack2(sB1[2 * (mg + 8 * j)], sB1[2 * (mg + 8 * j) + 1]);
                acc[0][j] = bia; acc[1][j] = bia;
            }
            const ull* xr0 = (const ull*)sXd + (t0 + 2 * tg) * 16;
            const ull* xr1 = xr0 + 16;
            #pragma unroll
            for (int we = 0; we < 48; we++) {
                ull xa = xr0[we], xb = xr1[we];
                #pragma unroll
                for (int j = 0; j < 4; j++) {
                    ull wv = *(const ull*)&sW1[we * 64 + 2 * (mg + 8 * j)];
                    ffma2(acc[0][j], xa, wv);
                    ffma2(acc[1][j], xb, wv);
                }
            }
            #pragma unroll
            for (int tl = 0; tl < 2; tl++) {
                int t = 2 * tg + tl;
                if (t < tc) {
                    float* hr = &sHd[t * 140];
                    #pragma unroll
                    for (int j = 0; j < 4; j++) {
                        float lo, hi; unpack2(acc[tl][j], lo, hi);
                        *(ull*)&hr[4 * (mg + 8 * j)]     = pack2(lo, lo);
                        *(ull*)&hr[4 * (mg + 8 * j) + 2] = pack2(hi, hi);
                    }
                }
            }
        }
        __syncthreads();
        // ---- conv2 + relu ----
        {
            ull acc[4][4];
            #pragma unroll
            for (int j = 0; j < 4; j++) {
                ull bia = pack2(sB2[2 * (cg + 16 * j)], sB2[2 * (cg + 16 * j) + 1]);
                #pragma unroll
                for (int i = 0; i < 4; i++) acc[i][j] = bia;
            }
            #pragma unroll
            for (int m = 0; m < 64; m++) {
                ull wv[4];
                #pragma unroll
                for (int j = 0; j < 4; j++)
                    wv[j] = *(const ull*)&sW2[m * 128 + 2 * (cg + 16 * j)];
                #pragma unroll
                for (int i = 0; i < 4; i++) {
                    ull hv = *(const ull*)&sHd[(4 * tgq + i) * 140 + 2 * m];
                    #pragma unroll
                    for (int j = 0; j < 4; j++) ffma2(acc[i][j], hv, wv[j]);
                }
            }
            #pragma unroll
            for (int i = 0; i < 4; i++) {
                int t = 4 * tgq + i;
                if (t < tc) {
                    float* ar = aug + (size_t)(t0 + t) * AUGS + 17;
                    #pragma unroll
                    for (int j = 0; j < 4; j++) {
                        float lo, hi; unpack2(acc[i][j], lo, hi);
                        int c = 2 * (cg + 16 * j);
                        ar[c]     = fmaxf(lo, 0.f);
                        ar[c + 1] = fmaxf(hi, 0.f);
                    }
                }
            }
        }
    }
}

// ============================================================
// K2: signature, double-buffered 16-deep tiles, row-split x2
// ============================================================
__global__ __launch_bounds__(256, 2) void k_sig()
{
    __shared__ float sD[2][16][168];
    __shared__ float sU[2][16][88];
    __shared__ float sA0[88];

    int n = blockIdx.x, tid = threadIdx.x;
    int r0 = blockIdx.y * 80;
    const float* aug = g_aug + (size_t)n * (TT * AUGS);
    float* sig = g_sig + (size_t)n * SIGS;

    if (tid < 88) sA0[tid] = (tid < 80 && r0 + tid < CH) ? aug[r0 + tid] : 0.f;
    if (blockIdx.y == 0) {
        if (tid < CH) sig[tid] = aug[253 * AUGS + tid] - aug[tid];   // s1
        if (tid >= 192 && tid < 192 + (SIGS - SIGK)) sig[SIGK + (tid - 192)] = 0.f;
    }

    int kk = tid >> 4, cx = tid & 15;
    int ty = tid >> 4, tx = tid & 15;

    // load tile 0 into regs
    float pa[10], pb[10];
    {
        const float* rr = aug + (size_t)kk * AUGS;
        #pragma unroll
        for (int s = 0; s < 10; s++) {
            int c = cx + 16 * s;
            bool ok = (c < CH);
            pa[s] = ok ? rr[c] : 0.f;
            pb[s] = ok ? rr[AUGS + c] : 0.f;
        }
    }
    __syncthreads();                       // sA0 ready
    #pragma unroll
    for (int s = 0; s < 10; s++) {
        int c = cx + 16 * s;
        sD[0][kk][c] = pb[s] - pa[s];
        unsigned cc = (unsigned)(c - r0);
        if (cc < 80u) sU[0][kk][cc] = 0.5f * (pa[s] + pb[s]) - sA0[cc];
    }
    __syncthreads();

    ull acc[5][5];
    #pragma unroll
    for (int r = 0; r < 5; r++)
        #pragma unroll
        for (int s = 0; s < 5; s++) acc[r][s] = 0ull;

    const int NTILE = 16;
    for (int it = 0; it < NTILE; it++) {
        int cur = it & 1;
        float na[10], nb[10];
        if (it + 1 < NTILE) {
            int t = 16 * (it + 1) + kk;
            bool okr = (t < 253);
            const float* rr = aug + (size_t)(okr ? t : 0) * AUGS;
            #pragma unroll
            for (int s = 0; s < 10; s++) {
                int c = cx + 16 * s;
                bool ok = okr && (c < CH);
                na[s] = ok ? rr[c] : 0.f;
                nb[s] = ok ? rr[AUGS + c] : 0.f;
            }
        }
        #pragma unroll
        for (int k2 = 0; k2 < 16; k2++) {
            ull d2[5];
            #pragma unroll
            for (int s = 0; s < 5; s++)
                d2[s] = *(const ull*)&sD[cur][k2][2 * (tx + 16 * s)];
            #pragma unroll
            for (int r = 0; r < 5; r++) {
                float u = sU[cur][k2][ty + 16 * r];
                ull uu = pack2(u, u);
                #pragma unroll
                for (int s = 0; s < 5; s++) ffma2(acc[r][s], uu, d2[s]);
            }
        }
        __syncthreads();
        if (it + 1 < NTILE) {
            int nxt = cur ^ 1;
            #pragma unroll
            for (int s = 0; s < 10; s++) {
                int c = cx + 16 * s;
                sD[nxt][kk][c] = nb[s] - na[s];
                unsigned cc = (unsigned)(c - r0);
                if (cc < 80u) sU[nxt][kk][cc] = 0.5f * (na[s] + nb[s]) - sA0[cc];
            }
        }
        __syncthreads();
    }

    #pragma unroll
    for (int r = 0; r < 5; r++) {
        int i = r0 + ty + 16 * r;
        if (i >= CH) continue;
        float* row = sig + 145 + i * 145;
        #pragma unroll
        for (int s = 0; s < 5; s++) {
            int j = 2 * (tx + 16 * s);
            float lo, hi; unpack2(acc[r][s], lo, hi);
            if (j < CH)     row[j]     = lo;
            if (j + 1 < CH) row[j + 1] = hi;
        }
    }
}

// ============================================================
// K3a: init out with bias
// ============================================================
__global__ void k_bias(const float* __restrict__ lb, float* __restrict__ out)
{
    int i = blockIdx.x * 256 + threadIdx.x;
    out[i] = lb[i & 255];
}

// ============================================================
// K3b: split-K GEMM, double-buffered (unchanged from R3)
// ============================================================
#define SPLITK 72
#define KCH    296

__global__ __launch_bounds__(256, 2) void k_gemm(
    const float* __restrict__ W, float* __restrict__ out)
{
    __shared__ float sAd[2][8][264];
    __shared__ float sB[2][8][132];

    int n0 = blockIdx.x * 128, o0 = blockIdx.y * 128;
    int kb = blockIdx.z * KCH;
    int kend = min(kb + KCH, SIGS);
    int nk = (kend - kb) >> 3;
    int tid = threadIdx.x, ty = tid >> 4, tx = tid & 15;

    int am = tid >> 1;
    int ak = (tid & 1) * 4;
    int bk = tid >> 5;
    int bo = (tid & 31) * 4;

    const float* aptr = &g_sig[(size_t)(n0 + am) * SIGS + ak];
    const float* bptr = &W[(size_t)bk * 256 + o0 + bo];

    ull acc[8][4];
    #pragma unroll
    for (int i = 0; i < 8; i++)
        #pragma unroll
        for (int j = 0; j < 4; j++) acc[i][j] = 0ull;

    float4 av = *(const float4*)(aptr + kb);
    float4 bv = make_float4(0.f, 0.f, 0.f, 0.f);
    if (kb + bk < SIGK) bv = *(const float4*)(bptr + (size_t)kb * 256);
    {
        float* d = &sAd[0][ak][2 * am];
        d[0] = av.x; d[1] = av.x; d += 264; d[0] = av.y; d[1] = av.y;
        d += 264; d[0] = av.z; d[1] = av.z; d += 264; d[0] = av.w; d[1] = av.w;
        *(float4*)&sB[0][bk][bo] = bv;
    }

    for (int it = 0; it < nk; it++) {
        int cur = it & 1;
        float4 av2, bv2;
        if (it + 1 < nk) {
            int k0 = kb + 8 * (it + 1);
            av2 = *(const float4*)(aptr + k0);
            bv2 = make_float4(0.f, 0.f, 0.f, 0.f);
            if (k0 + bk < SIGK) bv2 = *(const float4*)(bptr + (size_t)k0 * 256);
        }
        __syncthreads();
        #pragma unroll
        for (int kk = 0; kk < 8; kk++) {
            const float* arow = &sAd[cur][kk][16 * ty];
            ull a[8];
            #pragma unroll
            for (int i = 0; i < 8; i++) a[i] = *(const ull*)(arow + 2 * i);
            ulonglong2 bl = *(const ulonglong2*)&sB[cur][kk][4 * tx];
            ulonglong2 bh = *(const ulonglong2*)&sB[cur][kk][64 + 4 * tx];
            #pragma unroll
            for (int i = 0; i < 8; i++) {
                ffma2(acc[i][0], a[i], bl.x);
                ffma2(acc[i][1], a[i], bl.y);
                ffma2(acc[i][2], a[i], bh.x);
                ffma2(acc[i][3], a[i], bh.y);
            }
        }
        if (it + 1 < nk) {
            int nxt = cur ^ 1;
            float* d = &sAd[nxt][ak][2 * am];
            d[0] = av2.x; d[1] = av2.x; d += 264; d[0] = av2.y; d[1] = av2.y;
            d += 264; d[0] = av2.z; d[1] = av2.z; d += 264; d[0] = av2.w; d[1] = av2.w;
            *(float4*)&sB[nxt][bk][bo] = bv2;
        }
    }

    #pragma unroll
    for (int i = 0; i < 8; i++) {
        float* orow = out + (size_t)(n0 + 8 * ty + i) * 256 + o0;
        #pragma unroll
        for (int j = 0; j < 4; j++) {
            int c = (j < 2) ? (4 * tx + 2 * j) : (64 + 4 * tx + 2 * (j - 2));
            float lo, hi; unpack2(acc[i][j], lo, hi);
            atomicAdd(&orow[c], lo);
            atomicAdd(&orow[c + 1], hi);
        }
    }
}

// ============================================================
extern "C" void kernel_launch(void* const* d_in, const int* in_sizes, int n_in,
                              void* d_out, int out_size)
{
    const float* q  = (const float*)d_in[0];
    const float* w1 = (const float*)d_in[4];
    const float* b1 = (const float*)d_in[5];
    const float* w2 = (const float*)d_in[6];
    const float* b2 = (const float*)d_in[7];
    const float* lw = (const float*)d_in[8];
    const float* lb = (const float*)d_in[9];
    float* out = (float*)d_out;

    cudaFuncSetAttribute(k_front, cudaFuncAttributeMaxDynamicSharedMemorySize,
                         28608 * 4);
    k_front<<<NB, 256, 28608 * 4>>>(q, w1, b1, w2, b2);
    k_sig<<<dim3(NB, 2), 256>>>();
    k_bias<<<256, 256>>>(lb, out);
    k_gemm<<<dim3(2, 2, SPLITK), 256>>>(lw, out);
}